// round 3
// baseline (speedup 1.0000x reference)
#include <cuda_runtime.h>
#include <math.h>

#define DIN 4096
#define NH  4096

// One warp per hidden element j. Computes all four gate pre-activations:
//   z_i = Wih[j]·x      + Whh[j]·h      + bih[j]      + bhh[j]
//   z_f = Wih[nh+j]·x   + Whh[nh+j]·h   + bih[nh+j]   + bhh[nh+j]
//   z_g = Wih[2nh+j]·x  + Whh[2nh+j]·h  + bih[2nh+j]  + bhh[2nh+j]
//   z_o = Wih[2nh+j]·x  + Whh[3nh+j]·h  + bih[3nh+j]  + bhh[3nh+j]
// Reference quirk: Wio aliases the Wig slice (Wih[2nh:3nh]), so z_o reuses
// the g-row x-accumulator; Wih[3nh:4nh] is never read. 7 weight rows/warp,
// 448 MB total DRAM — the floor for this problem.
// out = [it | ft | gt | ot | ct | ht], 6*NH floats.

__device__ __forceinline__ float warp_sum(float v) {
    #pragma unroll
    for (int off = 16; off > 0; off >>= 1)
        v += __shfl_xor_sync(0xFFFFFFFFu, v, off);
    return v;
}

__device__ __forceinline__ float sigmoidf_(float v) {
    return 1.0f / (1.0f + __expf(-v));
}

__device__ __forceinline__ void fma2(float& acc_lo, float& acc_hi,
                                     const float4 w, const float4 v) {
    // two independent chains per dot product (halves FMA serial latency)
    acc_lo += w.x * v.x + w.y * v.y;
    acc_hi += w.z * v.z + w.w * v.w;
}

__global__ __launch_bounds__(128) void lstm_fused_kernel(
    const float* __restrict__ x,
    const float* __restrict__ h,
    const float* __restrict__ c,
    const float* __restrict__ Wih,
    const float* __restrict__ Whh,
    const float* __restrict__ bih,
    const float* __restrict__ bhh,
    float* __restrict__ out)
{
    const int warp = (blockIdx.x * blockDim.x + threadIdx.x) >> 5;
    const int lane = threadIdx.x & 31;
    if (warp >= NH) return;

    const int j = warp;

    const float4* __restrict__ x4 = (const float4*)x;
    const float4* __restrict__ h4 = (const float4*)h;

    const float4* __restrict__ wi_x = (const float4*)(Wih + (size_t)j * DIN);
    const float4* __restrict__ wf_x = (const float4*)(Wih + (size_t)(NH + j) * DIN);
    const float4* __restrict__ wg_x = (const float4*)(Wih + (size_t)(2 * NH + j) * DIN);

    const float4* __restrict__ wi_h = (const float4*)(Whh + (size_t)j * NH);
    const float4* __restrict__ wf_h = (const float4*)(Whh + (size_t)(NH + j) * NH);
    const float4* __restrict__ wg_h = (const float4*)(Whh + (size_t)(2 * NH + j) * NH);
    const float4* __restrict__ wo_h = (const float4*)(Whh + (size_t)(3 * NH + j) * NH);

    float ai0 = 0.f, ai1 = 0.f, af0 = 0.f, af1 = 0.f, ag0 = 0.f, ag1 = 0.f;

    // x-phase: 3 weight rows vs x. 1024 float4 per row, 32 per lane.
    #pragma unroll 4
    for (int i = lane; i < DIN / 4; i += 32) {
        const float4 xv = x4[i];
        const float4 a  = wi_x[i];
        const float4 b  = wf_x[i];
        const float4 g  = wg_x[i];
        fma2(ai0, ai1, a, xv);
        fma2(af0, af1, b, xv);
        fma2(ag0, ag1, g, xv);
    }

    float hi0 = 0.f, hi1 = 0.f, hf0 = 0.f, hf1 = 0.f;
    float hg0 = 0.f, hg1 = 0.f, ho0 = 0.f, ho1 = 0.f;

    // h-phase: 4 weight rows vs h.
    #pragma unroll 4
    for (int i = lane; i < NH / 4; i += 32) {
        const float4 hv = h4[i];
        const float4 a  = wi_h[i];
        const float4 b  = wf_h[i];
        const float4 g  = wg_h[i];
        const float4 o  = wo_h[i];
        fma2(hi0, hi1, a, hv);
        fma2(hf0, hf1, b, hv);
        fma2(hg0, hg1, g, hv);
        fma2(ho0, ho1, o, hv);
    }

    const float ai_x = warp_sum(ai0 + ai1);
    const float af_x = warp_sum(af0 + af1);
    const float ag_x = warp_sum(ag0 + ag1);
    const float ai_h = warp_sum(hi0 + hi1);
    const float af_h = warp_sum(hf0 + hf1);
    const float ag_h = warp_sum(hg0 + hg1);
    const float ao_h = warp_sum(ho0 + ho1);

    if (lane == 0) {
        const float zi = ai_x + ai_h + __ldg(bih + j)          + __ldg(bhh + j);
        const float zf = af_x + af_h + __ldg(bih + NH + j)     + __ldg(bhh + NH + j);
        const float zg = ag_x + ag_h + __ldg(bih + 2 * NH + j) + __ldg(bhh + 2 * NH + j);
        const float zo = ag_x + ao_h + __ldg(bih + 3 * NH + j) + __ldg(bhh + 3 * NH + j);

        const float it = sigmoidf_(zi);
        const float ft = sigmoidf_(zf);
        const float gt = tanhf(zg);
        const float ot = sigmoidf_(zo);
        const float ct = ft * __ldg(c + j) + it * gt;
        const float ht = ot * tanhf(ct);

        out[j]          = it;
        out[NH + j]     = ft;
        out[2 * NH + j] = gt;
        out[3 * NH + j] = ot;
        out[4 * NH + j] = ct;
        out[5 * NH + j] = ht;
    }
}

extern "C" void kernel_launch(void* const* d_in, const int* in_sizes, int n_in,
                              void* d_out, int out_size)
{
    // metadata order: x, h, c, Wih, Whh, bih, bhh
    const float* x   = (const float*)d_in[0];
    const float* h   = (const float*)d_in[1];
    const float* c   = (const float*)d_in[2];
    const float* Wih = (const float*)d_in[3];
    const float* Whh = (const float*)d_in[4];
    const float* bih = (const float*)d_in[5];
    const float* bhh = (const float*)d_in[6];
    float* out = (float*)d_out;

    // NH warps, 4 warps per 128-thread block -> 1024 blocks.
    const int threads = 128;
    const int blocks  = NH / (threads / 32);

    lstm_fused_kernel<<<blocks, threads>>>(x, h, c, Wih, Whh, bih, bhh, out);
}